// round 6
// baseline (speedup 1.0000x reference)
#include <cuda_runtime.h>
#include <cuda_bf16.h>

// QuantumConv2d on GB300 — single fused kernel, f32x2-packed math.
//
// Per 2x2 patch (x0,x1,x2,x3):
//   t_k = A[k&3] + B[k>>2]  (signed sums, sign + iff bit set, LSB-first)
//   phase_k = -(t/2 + t^2/4)          [global phase dropped]
//   d_k = exp(i phase_k)
//   y = WHT( uhat .* WHT(d) ),  uhat_s = exp(i/2 sum_q (2 s_q - 1) w_q) / 64
//   state_{F(j)} = y_j, F = CNOT-ring perm {0,14,15,1,13,3,2,12,9,7,6,8,4,10,11,5}
//   out_q = sum_{j: bit(3-q) of F(j)} |y_j|^2

#define PK2(d, lo, hi)   asm("mov.b64 %0, {%1, %2};" : "=l"(d) : "f"(lo), "f"(hi))
#define UPK2(lo, hi, d)  asm("mov.b64 {%0, %1}, %2;" : "=f"(lo), "=f"(hi) : "l"(d))
#define ADD2(d, a, b)    asm("add.rn.f32x2 %0, %1, %2;" : "=l"(d) : "l"(a), "l"(b))
#define MUL2(d, a, b)    asm("mul.rn.f32x2 %0, %1, %2;" : "=l"(d) : "l"(a), "l"(b))
#define FMA2(d, a, b, c) asm("fma.rn.f32x2 %0, %1, %2, %3;" : "=l"(d) : "l"(a), "l"(b), "l"(c))

__global__ __launch_bounds__(256) void qconv_kernel(const float* __restrict__ x,
                                                    const float* __restrict__ w,
                                                    float4* __restrict__ out) {
    __shared__ unsigned long long s_urr[16];   // (ur, ur)  packed, 1/64 folded in
    __shared__ unsigned long long s_unii[16];  // (-ui, ui) packed

    // in-block uhat setup (replaces the separate setup kernel + its launch cost)
    if (threadIdx.x < 16) {
        int s = threadIdx.x;
        float th = 0.0f;
        #pragma unroll
        for (int q = 0; q < 4; q++)
            th += ((s >> q) & 1) ? w[q] : -w[q];
        th *= 0.5f;
        float sn, cs;
        __sincosf(th, &sn, &cs);
        cs *= 0.015625f; sn *= 0.015625f;
        unsigned long long rr, nii;
        PK2(rr, cs, cs);
        float nsn = -sn;
        PK2(nii, nsn, sn);
        s_urr[s] = rr; s_unii[s] = nii;
    }
    __syncthreads();

    int tid = blockIdx.x * blockDim.x + threadIdx.x;   // = b*16384 + jj*128 + ii
    int b  = tid >> 14;
    int jj = (tid >> 7) & 127;
    int ii = tid & 127;

    const float* p = x + (b << 16) + (jj << 9) + (ii << 1);
    float2 a01 = *(const float2*)(p);
    float2 a23 = *(const float2*)(p + 256);
    float x0 = a01.x, x1 = a01.y, x2 = a23.x, x3 = a23.y;

    float A0 = -x0 - x1, A1 =  x0 - x1, A2 = -x0 + x1, A3 =  x0 + x1;
    float Bv[4] = {-x2 - x3,  x2 - x3, -x2 + x3,  x2 + x3};

    unsigned long long C_N025, C_N05, NEG1;
    asm("mov.b64 %0, 0xBE800000BE800000;" : "=l"(C_N025));  // (-0.25, -0.25)
    asm("mov.b64 %0, 0xBF000000BF000000;" : "=l"(C_N05));   // (-0.5,  -0.5)
    asm("mov.b64 %0, 0xBF800000BF800000;" : "=l"(NEG1));    // (-1,    -1)

    unsigned long long pA01, pA23;
    PK2(pA01, A0, A1);
    PK2(pA23, A2, A3);

    // phases + cis, packed pairwise: ph = t * (-0.25 t - 0.5)
    unsigned long long v[16];   // packed (re, im)
    #pragma unroll
    for (int j = 0; j < 4; j++) {
        unsigned long long pB;
        PK2(pB, Bv[j], Bv[j]);
        unsigned long long t0, t1, f0, f1, q0, q1;
        ADD2(t0, pA01, pB);
        ADD2(t1, pA23, pB);
        FMA2(f0, t0, C_N025, C_N05);
        FMA2(f1, t1, C_N025, C_N05);
        MUL2(q0, t0, f0);
        MUL2(q1, t1, f1);
        float pa, pb, pc, pd;
        UPK2(pa, pb, q0);
        UPK2(pc, pd, q1);
        float s0, c0, s1, c1, s2, c2, s3, c3;
        __sincosf(pa, &s0, &c0);
        __sincosf(pb, &s1, &c1);
        __sincosf(pc, &s2, &c2);
        __sincosf(pd, &s3, &c3);
        PK2(v[4*j + 0], c0, s0);
        PK2(v[4*j + 1], c1, s1);
        PK2(v[4*j + 2], c2, s2);
        PK2(v[4*j + 3], c3, s3);
    }

    // WHT #1
    #pragma unroll
    for (int m = 1; m < 16; m <<= 1) {
        #pragma unroll
        for (int k = 0; k < 16; k++) {
            if (!(k & m)) {
                unsigned long long a = v[k], bb = v[k | m], s, d;
                ADD2(s, a, bb);
                FMA2(d, bb, NEG1, a);
                v[k] = s; v[k | m] = d;
            }
        }
    }

    // packed pointwise complex multiply by uhat:
    // (re,im)*(ur+i ui) = (ur*re - ui*im, ur*im + ui*re)
    //                   = v*(ur,ur) + (im,re)*(-ui,ui)
    #pragma unroll
    for (int s = 0; s < 16; s++) {
        unsigned long long urr = s_urr[s], unii = s_unii[s];
        float re, im;
        UPK2(re, im, v[s]);
        unsigned long long sw, m;
        PK2(sw, im, re);
        MUL2(m, sw, unii);
        FMA2(v[s], v[s], urr, m);
    }

    // WHT #2
    #pragma unroll
    for (int m = 1; m < 16; m <<= 1) {
        #pragma unroll
        for (int k = 0; k < 16; k++) {
            if (!(k & m)) {
                unsigned long long a = v[k], bb = v[k | m], s, d;
                ADD2(s, a, bb);
                FMA2(d, bb, NEG1, a);
                v[k] = s; v[k | m] = d;
            }
        }
    }

    // probabilities
    float pr[16];
    #pragma unroll
    for (int j = 0; j < 16; j++) {
        float re, im;
        UPK2(re, im, v[j]);
        pr[j] = fmaf(re, re, im * im);
    }

    // grouped accumulation through F = {0,14,15,1,13,3,2,12,9,7,6,8,4,10,11,5}
    // T_k = sum of pr[j] with F(j)>>2 == k ; U_k with F(j)&3 == k
    float T1 = pr[9]  + pr[10] + pr[12] + pr[15];
    float T2 = pr[8]  + pr[11] + pr[13] + pr[14];
    float T3 = pr[1]  + pr[2]  + pr[4]  + pr[7];
    float U1 = pr[3]  + pr[4]  + pr[8]  + pr[15];
    float U2 = pr[1]  + pr[6]  + pr[10] + pr[13];
    float U3 = pr[2]  + pr[5]  + pr[9]  + pr[14];
    float o0 = T2 + T3;   // bit 3 of F(j)
    float o1 = T1 + T3;   // bit 2
    float o2 = U2 + U3;   // bit 1
    float o3 = U1 + U3;   // bit 0

    out[tid] = make_float4(o0, o1, o2, o3);
}

extern "C" void kernel_launch(void* const* d_in, const int* in_sizes, int n_in,
                              void* d_out, int out_size) {
    const float* x = (const float*)d_in[0];
    const float* w = (const float*)d_in[1];
    if (n_in >= 2 && in_sizes[0] == 4) {   // robustness if metadata order differs
        x = (const float*)d_in[1];
        w = (const float*)d_in[0];
    }
    qconv_kernel<<<4096, 256>>>(x, w, (float4*)d_out);
}

// round 7
// speedup vs baseline: 1.1218x; 1.1218x over previous
#include <cuda_runtime.h>
#include <cuda_bf16.h>

// QuantumConv2d on GB300 — direct tensor-product RX application (no WHT, no smem).
//
// Per 2x2 patch (x0,x1,x2,x3):
//   t_k = A[k&3] + B[k>>2]  (signed sums, sign + iff bit k set, LSB-first)
//   phase_k = -(t/2 + t^2/4)          [global phase dropped]
//   d_k = exp(i phase_k)
//   y = (RX(w3) (x) RX(w2) (x) RX(w1) (x) RX(w0)) d, applied as 4 commuting
//       single-qubit stages: pair (a, b=a^2^q): y_a = c a - i s b, y_b = -i s a + c b
//       with c=cos(w_q/2), s=sin(w_q/2).  Packed complex (re,im):
//       -i s b = (s*bi, -s*br) = (s,-s) .* swap(b)
//   0.25 initial-state amplitude folded into stage-3 coefficients.
//   state_{F(j)} = y_j, F = CNOT-ring perm {0,14,15,1,13,3,2,12,9,7,6,8,4,10,11,5}
//   out_q = sum_{j: bit(3-q) of F(j)} |y_j|^2

#define PK2(d, lo, hi)   asm("mov.b64 %0, {%1, %2};" : "=l"(d) : "f"(lo), "f"(hi))
#define UPK2(lo, hi, d)  asm("mov.b64 {%0, %1}, %2;" : "=f"(lo), "=f"(hi) : "l"(d))
#define MUL2(d, a, b)    asm("mul.rn.f32x2 %0, %1, %2;" : "=l"(d) : "l"(a), "l"(b))
#define FMA2(d, a, b, c) asm("fma.rn.f32x2 %0, %1, %2, %3;" : "=l"(d) : "l"(a), "l"(b), "l"(c))

__global__ __launch_bounds__(256) void qconv_kernel(const float* __restrict__ x,
                                                    const float* __restrict__ w,
                                                    float4* __restrict__ out) {
    // per-thread RX coefficients (w is uniform -> const-cached LDG)
    float c[4], s[4];
    #pragma unroll
    for (int q = 0; q < 4; q++)
        __sincosf(0.5f * w[q], &s[q], &c[q]);
    // fold the 0.25 initial-state amplitude into the last stage
    c[3] *= 0.25f;
    s[3] *= 0.25f;

    int tid = blockIdx.x * blockDim.x + threadIdx.x;   // = b*16384 + jj*128 + ii
    int b  = tid >> 14;
    int jj = (tid >> 7) & 127;
    int ii = tid & 127;

    const float* p = x + (b << 16) + (jj << 9) + (ii << 1);
    float2 a01 = *(const float2*)(p);
    float2 a23 = *(const float2*)(p + 256);
    float x0 = a01.x, x1 = a01.y, x2 = a23.x, x3 = a23.y;

    float A[4] = {-x0 - x1,  x0 - x1, -x0 + x1,  x0 + x1};
    float B[4] = {-x2 - x3,  x2 - x3, -x2 + x3,  x2 + x3};

    // phases + cis (scalar path — fewer dependency stalls than packed)
    unsigned long long v[16];   // packed (re, im)
    #pragma unroll
    for (int k = 0; k < 16; k++) {
        float t  = A[k & 3] + B[k >> 2];
        float ph = t * fmaf(-0.25f, t, -0.5f);   // -(t/2 + t^2/4)
        float sn, cs;
        __sincosf(ph, &sn, &cs);
        PK2(v[k], cs, sn);
    }

    // 4 single-qubit RX stages (commuting)
    #pragma unroll
    for (int q = 0; q < 4; q++) {
        int m = 1 << q;
        float cq = c[q], sq = s[q], nsq = -s[q];
        unsigned long long C2, S2;
        PK2(C2, cq, cq);      // (c,  c)
        PK2(S2, sq, nsq);     // (s, -s)
        #pragma unroll
        for (int k = 0; k < 16; k++) {
            if (!(k & m)) {
                unsigned long long a = v[k], bb = v[k | m];
                float ar, ai, br, bi;
                UPK2(ar, ai, a);
                UPK2(br, bi, bb);
                unsigned long long sa, sb;        // swapped halves (ALU MOVs)
                PK2(sa, ai, ar);
                PK2(sb, bi, br);
                unsigned long long ta, tb, ya, yb;
                MUL2(ta, a, C2);
                MUL2(tb, bb, C2);
                FMA2(ya, sb, S2, ta);             // c*a + (s*bi, -s*br)
                FMA2(yb, sa, S2, tb);             // c*b + (s*ai, -s*ar)
                v[k] = ya; v[k | m] = yb;
            }
        }
    }

    // probabilities
    float pr[16];
    #pragma unroll
    for (int j = 0; j < 16; j++) {
        float re, im;
        UPK2(re, im, v[j]);
        pr[j] = fmaf(re, re, im * im);
    }

    // grouped accumulation through F = {0,14,15,1,13,3,2,12,9,7,6,8,4,10,11,5}
    float T1 = pr[9]  + pr[10] + pr[12] + pr[15];
    float T2 = pr[8]  + pr[11] + pr[13] + pr[14];
    float T3 = pr[1]  + pr[2]  + pr[4]  + pr[7];
    float U1 = pr[3]  + pr[4]  + pr[8]  + pr[15];
    float U2 = pr[1]  + pr[6]  + pr[10] + pr[13];
    float U3 = pr[2]  + pr[5]  + pr[9]  + pr[14];
    float o0 = T2 + T3;   // bit 3 of F(j)
    float o1 = T1 + T3;   // bit 2
    float o2 = U2 + U3;   // bit 1
    float o3 = U1 + U3;   // bit 0

    out[tid] = make_float4(o0, o1, o2, o3);
}

extern "C" void kernel_launch(void* const* d_in, const int* in_sizes, int n_in,
                              void* d_out, int out_size) {
    const float* x = (const float*)d_in[0];
    const float* w = (const float*)d_in[1];
    if (n_in >= 2 && in_sizes[0] == 4) {   // robustness if metadata order differs
        x = (const float*)d_in[1];
        w = (const float*)d_in[0];
    }
    qconv_kernel<<<4096, 256>>>(x, w, (float4*)d_out);
}